// round 14
// baseline (speedup 1.0000x reference)
#include <cuda_runtime.h>
#include <cstdint>

#define NGT 100
#define TPB 256
#define APT 4
#define ANCHORS_PER_BLOCK (APT * TPB)
#define BMAX 64
#define AMAX 8732

// Scratch (allocation-free: __device__ globals)
__device__ unsigned long long g_gtbest[BMAX * NGT];
__device__ float g_bestv[BMAX * AMAX];
__device__ int   g_besti[BMAX * AMAX];

// Seed = (iou bits 0) << 32 | ~anchor0  -> "iou 0 at anchor 0", matching
// jnp.argmax of an all-zero column (first index = 0). ~0 beats every other
// ~a, so zero-only submissions can never displace it.
#define GTBEST_SEED 0x00000000FFFFFFFFull

__global__ void init_kernel(int total) {
    int i = blockIdx.x * blockDim.x + threadIdx.x;
    if (i < total) g_gtbest[i] = GTBEST_SEED;
}

// Branch-free correctly-rounded fp32 division (Markstein sequence).
// Bit-identical to div.rn.f32 for normal operands and +0 numerator:
// exactly the ptxas fast path for __fdiv_rn, minus the FCHK guard.
// Valid here: uni in [~1e-4, 1.2] (normal), inter in {+0} U [~1e-18, 0.04],
// quotient normal or +0 — no denormal/overflow/NaN cases can occur.
__device__ __forceinline__ float div_rn_fast(float n, float d) {
    float r;
    asm("rcp.approx.f32 %0, %1;" : "=f"(r) : "f"(d));
    float e  = __fmaf_rn(-d, r, 1.0f);
    float r1 = __fmaf_rn(r, e, r);
    float q  = __fmul_rn(n, r1);
    float rem = __fmaf_rn(-d, q, n);
    return __fmaf_rn(rem, r1, q);
}

// Kernel 1: IoU + per-anchor argmax over gts + per-gt argmax over anchors.
// Dense and branch-free in the hot loop; lives on ILP + occupancy.
// __launch_bounds__(256, 4) caps regs at 64 -> 4 blocks/SM -> 8 warps/SMSP
// to cover the MUFU/LDS/REDUX latency (was likely 2 blocks/SM before).
// All __f*_rn arithmetic is bit-exact vs XLA — load-bearing for ulp-level
// argmax ties.
__global__ __launch_bounds__(TPB, 4) void iou_kernel(
    const float* __restrict__ gt_boxes,     // [B, NGT, 4] xyxy
    const float* __restrict__ anchors_xyxy, // [A, 4]
    int A)
{
    const int b = blockIdx.y;
    __shared__ float4 sgt[NGT];
    __shared__ float  sga[NGT];
    const int tid = threadIdx.x;

    if (tid < NGT) {
        float4 g = reinterpret_cast<const float4*>(gt_boxes)[b * NGT + tid];
        sgt[tid] = g;
        sga[tid] = __fmul_rn(__fsub_rn(g.z, g.x), __fsub_rn(g.w, g.y));
    }
    __syncthreads();

    const int a0 = blockIdx.x * ANCHORS_PER_BLOCK + tid;
    const bool lane0 = (tid & 31) == 0;

    float4 anc[APT];
    float  aarea[APT];
#pragma unroll
    for (int k = 0; k < APT; k++) {
        int a = a0 + k * TPB;
        if (a < A) {
            anc[k] = reinterpret_cast<const float4*>(anchors_xyxy)[a];
            aarea[k] = __fmul_rn(__fsub_rn(anc[k].z, anc[k].x),
                                 __fsub_rn(anc[k].w, anc[k].y));
        } else {
            // Degenerate far-away box: inter == 0 with any gt -> iou == +0,
            // never wins a strict-> argmax.
            anc[k] = make_float4(2.0f, 2.0f, 2.0f, 2.0f);
            aarea[k] = 0.0f;
        }
    }

    float bestv[APT];
    int   besti[APT];
#pragma unroll
    for (int k = 0; k < APT; k++) { bestv[k] = 0.0f; besti[k] = 0; }

    unsigned long long* gt_row = &g_gtbest[b * NGT];

#pragma unroll 4
    for (int n = 0; n < NGT; n++) {
        const float4 g = sgt[n];
        const float  ga = sga[n];
        float rowbest = 0.0f;
        int   rowk = 0;
#pragma unroll
        for (int k = 0; k < APT; k++) {
            float ltx = fmaxf(anc[k].x, g.x);
            float lty = fmaxf(anc[k].y, g.y);
            float rbx = fminf(anc[k].z, g.z);
            float rby = fminf(anc[k].w, g.w);
            float w = fmaxf(__fsub_rn(rbx, ltx), 0.0f);
            float h = fmaxf(__fsub_rn(rby, lty), 0.0f);
            float inter = __fmul_rn(w, h);
            float uni = __fsub_rn(__fadd_rn(aarea[k], ga), inter);
            float iou = div_rn_fast(inter, uni);   // inter==0 -> +0 exactly
            // per-anchor argmax over n: strict > == first-index tie-break
            if (iou > bestv[k]) { bestv[k] = iou; besti[k] = n; }
            // per-gt argmax over this thread's anchors (k ascending => anchor
            // ascending; strict > keeps smallest anchor index on exact ties)
            if (iou > rowbest) { rowbest = iou; rowk = k; }
        }
        // Warp argmax via 2x REDUX, unguarded:
        //  - rowbest >= 0 and __float_as_uint(+0) == 0 -> empty lanes
        //    contribute 0 naturally (iou > 0 => bits u32-monotone).
        //  - tild = ~anchor: among tied lanes max ~a == min anchor index
        //    (matches jnp.argmax first-occurrence).
        //  - all-zero warp submits (0, ~min_a), losing to seed (0, ~0).
        unsigned bits = __float_as_uint(rowbest);
        unsigned tild = ~(unsigned)(a0 + rowk * TPB);
        unsigned maxbits = __reduce_max_sync(0xFFFFFFFFu, bits);
        unsigned cand = (bits == maxbits) ? tild : 0u;
        unsigned maxtild = __reduce_max_sync(0xFFFFFFFFu, cand);
        if (lane0) {
            unsigned long long packed =
                ((unsigned long long)maxbits << 32) | maxtild;
            atomicMax(&gt_row[n], packed);
        }
    }

    const int base = b * A + a0;
#pragma unroll
    for (int k = 0; k < APT; k++) {
        int a = a0 + k * TPB;
        if (a < A) {
            g_bestv[base + k * TPB] = bestv[k];
            g_besti[base + k * TPB] = besti[k];
        }
    }
}

// Kernel 2: scatter override. For each gt n, set its best anchor's match to
// (n, 2.0). On duplicate anchors, last n wins (in-order scatter semantics).
__global__ void override_kernel(int A) {
    const int b = blockIdx.x;
    __shared__ int sa[NGT];
    const int t = threadIdx.x;
    if (t < NGT) {
        unsigned long long p = g_gtbest[b * NGT + t];
        sa[t] = (int)(~(unsigned int)p);  // low 32 bits = ~anchor_idx
    }
    __syncthreads();
    if (t < NGT) {
        int a = sa[t];
        bool last = true;
        for (int m = t + 1; m < NGT; m++)
            if (sa[m] == a) last = false;
        if (last) {
            g_besti[b * A + a] = t;
            g_bestv[b * A + a] = 2.0f;
        }
    }
}

// Kernel 3: gather + encode. Output layout (float32, concatenated tuple order):
// [0, B*A)        encoded_labels
// [B*A, 5*B*A)    encoded (B, A, 4)
// [5*B*A, 6*B*A)  pos_mask (1.0/0.0)
__global__ __launch_bounds__(256) void encode_kernel(
    const int*   __restrict__ gt_labels,      // [B, NGT]
    const float* __restrict__ gt_boxes,       // [B, NGT, 4] xyxy
    const float* __restrict__ anchors_cxcywh, // [A, 4]
    float* __restrict__ out,
    int A, int B)
{
    const int a = blockIdx.x * blockDim.x + threadIdx.x;
    if (a >= A) return;
    const int b = blockIdx.y;
    const int i = b * A + a;
    const int total = B * A;

    const float v = g_bestv[i];
    const int   n = g_besti[i];
    const bool pos = (v > 0.5f);

    float4 g = reinterpret_cast<const float4*>(gt_boxes)[b * NGT + n];
    float4 anc = reinterpret_cast<const float4*>(anchors_cxcywh)[a];

    float gcx = __fmul_rn(__fadd_rn(g.x, g.z), 0.5f);   // == /2 exactly
    float gcy = __fmul_rn(__fadd_rn(g.y, g.w), 0.5f);
    float gw = __fsub_rn(g.z, g.x);
    float gh = __fsub_rn(g.w, g.y);

    float ex = __fdiv_rn(__fsub_rn(gcx, anc.x), anc.z);
    float ey = __fdiv_rn(__fsub_rn(gcy, anc.y), anc.w);
    float ew = logf(__fdiv_rn(__fadd_rn(gw, 1e-6f), __fadd_rn(anc.z, 1e-6f)));
    float eh = logf(__fdiv_rn(__fadd_rn(gh, 1e-6f), __fadd_rn(anc.w, 1e-6f)));

    out[i] = pos ? (float)gt_labels[b * NGT + n] : 0.0f;
    reinterpret_cast<float4*>(out + total)[i] = make_float4(ex, ey, ew, eh);
    out[5 * total + i] = pos ? 1.0f : 0.0f;
}

extern "C" void kernel_launch(void* const* d_in, const int* in_sizes, int n_in,
                              void* d_out, int out_size)
{
    const int*   gt_labels      = (const int*)d_in[0];
    const float* gt_boxes       = (const float*)d_in[1];
    const float* anchors_cxcywh = (const float*)d_in[2];
    const float* anchors_xyxy   = (const float*)d_in[3];

    const int A = in_sizes[2] / 4;
    const int B = in_sizes[0] / NGT;

    const int chunks = (A + ANCHORS_PER_BLOCK - 1) / ANCHORS_PER_BLOCK;

    init_kernel<<<(B * NGT + 255) / 256, 256>>>(B * NGT);
    iou_kernel<<<dim3(chunks, B), TPB>>>(gt_boxes, anchors_xyxy, A);
    override_kernel<<<B, 128>>>(A);
    encode_kernel<<<dim3((A + 255) / 256, B), 256>>>(gt_labels, gt_boxes,
                                                     anchors_cxcywh,
                                                     (float*)d_out, A, B);
}

// round 17
// speedup vs baseline: 1.6214x; 1.6214x over previous
#include <cuda_runtime.h>
#include <cstdint>

#define NGT 100
#define TPB 256
#define APT 4
#define ANCHORS_PER_BLOCK (APT * TPB)
#define BMAX 64
#define AMAX 8732

// Scratch (allocation-free: __device__ globals)
__device__ unsigned long long g_gtbest[BMAX * NGT];
__device__ float g_bestv[BMAX * AMAX];
__device__ int   g_besti[BMAX * AMAX];

// Seed = (iou bits 0) << 32 | ~anchor0  -> "iou 0 at anchor 0", matching
// jnp.argmax of an all-zero column (first index = 0). ~0 beats every other
// ~a, so zero-only submissions can never displace it.
#define GTBEST_SEED 0x00000000FFFFFFFFull

__global__ void init_kernel(int total) {
    int i = blockIdx.x * blockDim.x + threadIdx.x;
    if (i < total) g_gtbest[i] = GTBEST_SEED;
}

// Branch-free correctly-rounded fp32 division (Markstein sequence).
// Bit-identical to div.rn.f32 for normal operands and +0 numerator:
// exactly the ptxas fast path for __fdiv_rn, minus the FCHK guard.
// Valid here: uni in [~1e-4, 1.2] (normal), inter in {+0} U [~1e-14, 0.04],
// quotient normal or +0 — no denormal/overflow/NaN cases can occur.
__device__ __forceinline__ float div_rn_fast(float n, float d) {
    float r;
    asm("rcp.approx.f32 %0, %1;" : "=f"(r) : "f"(d));
    float e  = __fmaf_rn(-d, r, 1.0f);
    float r1 = __fmaf_rn(r, e, r);
    float q  = __fmul_rn(n, r1);
    float rem = __fmaf_rn(-d, q, n);
    return __fmaf_rn(rem, r1, q);
}

// Kernel 1: IoU + per-anchor argmax over gts + per-gt argmax over anchors.
// Dense and branch-free in the hot loop; lives on ILP + occupancy.
// __launch_bounds__(256, 3): cap 85 regs -> 3 blocks/SM (6 warps/SMSP).
// The 64-reg cap (minBlocks=4) spilled and regressed; 85 should fit the
// ~28 long-lived regs + Markstein temps without spills.
// All __f*_rn arithmetic is bit-exact vs XLA — load-bearing for ulp-level
// argmax ties.
__global__ __launch_bounds__(TPB, 3) void iou_kernel(
    const float* __restrict__ gt_boxes,     // [B, NGT, 4] xyxy
    const float* __restrict__ anchors_xyxy, // [A, 4]
    int A)
{
    const int b = blockIdx.y;
    __shared__ float4 sgt[NGT];
    __shared__ float  sga[NGT];
    const int tid = threadIdx.x;

    if (tid < NGT) {
        float4 g = reinterpret_cast<const float4*>(gt_boxes)[b * NGT + tid];
        sgt[tid] = g;
        sga[tid] = __fmul_rn(__fsub_rn(g.z, g.x), __fsub_rn(g.w, g.y));
    }
    __syncthreads();

    const int a0 = blockIdx.x * ANCHORS_PER_BLOCK + tid;
    const bool lane0 = (tid & 31) == 0;

    float4 anc[APT];
    float  aarea[APT];
#pragma unroll
    for (int k = 0; k < APT; k++) {
        int a = a0 + k * TPB;
        if (a < A) {
            anc[k] = reinterpret_cast<const float4*>(anchors_xyxy)[a];
            aarea[k] = __fmul_rn(__fsub_rn(anc[k].z, anc[k].x),
                                 __fsub_rn(anc[k].w, anc[k].y));
        } else {
            // Degenerate far-away box: inter == 0 with any gt -> iou == +0,
            // never wins a strict-> argmax.
            anc[k] = make_float4(2.0f, 2.0f, 2.0f, 2.0f);
            aarea[k] = 0.0f;
        }
    }

    float bestv[APT];
    int   besti[APT];
#pragma unroll
    for (int k = 0; k < APT; k++) { bestv[k] = 0.0f; besti[k] = 0; }

    unsigned long long* gt_row = &g_gtbest[b * NGT];

#pragma unroll 4
    for (int n = 0; n < NGT; n++) {
        const float4 g = sgt[n];
        const float  ga = sga[n];
        float rowbest = 0.0f;
        int   rowk = 0;
#pragma unroll
        for (int k = 0; k < APT; k++) {
            float ltx = fmaxf(anc[k].x, g.x);
            float lty = fmaxf(anc[k].y, g.y);
            float rbx = fminf(anc[k].z, g.z);
            float rby = fminf(anc[k].w, g.w);
            float w = fmaxf(__fsub_rn(rbx, ltx), 0.0f);
            float h = fmaxf(__fsub_rn(rby, lty), 0.0f);
            float inter = __fmul_rn(w, h);
            float uni = __fsub_rn(__fadd_rn(aarea[k], ga), inter);
            float iou = div_rn_fast(inter, uni);   // inter==0 -> +0 exactly
            // per-anchor argmax over n: strict > == first-index tie-break
            if (iou > bestv[k]) { bestv[k] = iou; besti[k] = n; }
            // per-gt argmax over this thread's anchors (k ascending => anchor
            // ascending; strict > keeps smallest anchor index on exact ties)
            if (iou > rowbest) { rowbest = iou; rowk = k; }
        }
        // Warp argmax via 2x REDUX, unguarded:
        //  - rowbest >= 0 and __float_as_uint(+0) == 0 -> empty lanes
        //    contribute 0 naturally (iou > 0 => bits u32-monotone).
        //  - tild = ~anchor: among tied lanes max ~a == min anchor index
        //    (matches jnp.argmax first-occurrence).
        //  - all-zero warp submits (0, ~min_a), losing to seed (0, ~0).
        unsigned bits = __float_as_uint(rowbest);
        unsigned tild = ~(unsigned)(a0 + rowk * TPB);
        unsigned maxbits = __reduce_max_sync(0xFFFFFFFFu, bits);
        unsigned cand = (bits == maxbits) ? tild : 0u;
        unsigned maxtild = __reduce_max_sync(0xFFFFFFFFu, cand);
        if (lane0) {
            unsigned long long packed =
                ((unsigned long long)maxbits << 32) | maxtild;
            atomicMax(&gt_row[n], packed);
        }
    }

    const int base = b * A + a0;
#pragma unroll
    for (int k = 0; k < APT; k++) {
        int a = a0 + k * TPB;
        if (a < A) {
            g_bestv[base + k * TPB] = bestv[k];
            g_besti[base + k * TPB] = besti[k];
        }
    }
}

// Kernel 2: scatter override. For each gt n, set its best anchor's match to
// (n, 2.0). On duplicate anchors, last n wins (in-order scatter semantics).
__global__ void override_kernel(int A) {
    const int b = blockIdx.x;
    __shared__ int sa[NGT];
    const int t = threadIdx.x;
    if (t < NGT) {
        unsigned long long p = g_gtbest[b * NGT + t];
        sa[t] = (int)(~(unsigned int)p);  // low 32 bits = ~anchor_idx
    }
    __syncthreads();
    if (t < NGT) {
        int a = sa[t];
        bool last = true;
        for (int m = t + 1; m < NGT; m++)
            if (sa[m] == a) last = false;
        if (last) {
            g_besti[b * A + a] = t;
            g_bestv[b * A + a] = 2.0f;
        }
    }
}

// Kernel 3: gather + encode. Output layout (float32, concatenated tuple order):
// [0, B*A)        encoded_labels
// [B*A, 5*B*A)    encoded (B, A, 4)
// [5*B*A, 6*B*A)  pos_mask (1.0/0.0)
__global__ __launch_bounds__(256) void encode_kernel(
    const int*   __restrict__ gt_labels,      // [B, NGT]
    const float* __restrict__ gt_boxes,       // [B, NGT, 4] xyxy
    const float* __restrict__ anchors_cxcywh, // [A, 4]
    float* __restrict__ out,
    int A, int B)
{
    const int a = blockIdx.x * blockDim.x + threadIdx.x;
    if (a >= A) return;
    const int b = blockIdx.y;
    const int i = b * A + a;
    const int total = B * A;

    const float v = g_bestv[i];
    const int   n = g_besti[i];
    const bool pos = (v > 0.5f);

    float4 g = reinterpret_cast<const float4*>(gt_boxes)[b * NGT + n];
    float4 anc = reinterpret_cast<const float4*>(anchors_cxcywh)[a];

    float gcx = __fmul_rn(__fadd_rn(g.x, g.z), 0.5f);   // == /2 exactly
    float gcy = __fmul_rn(__fadd_rn(g.y, g.w), 0.5f);
    float gw = __fsub_rn(g.z, g.x);
    float gh = __fsub_rn(g.w, g.y);

    float ex = __fdiv_rn(__fsub_rn(gcx, anc.x), anc.z);
    float ey = __fdiv_rn(__fsub_rn(gcy, anc.y), anc.w);
    float ew = logf(__fdiv_rn(__fadd_rn(gw, 1e-6f), __fadd_rn(anc.z, 1e-6f)));
    float eh = logf(__fdiv_rn(__fadd_rn(gh, 1e-6f), __fadd_rn(anc.w, 1e-6f)));

    out[i] = pos ? (float)gt_labels[b * NGT + n] : 0.0f;
    reinterpret_cast<float4*>(out + total)[i] = make_float4(ex, ey, ew, eh);
    out[5 * total + i] = pos ? 1.0f : 0.0f;
}

extern "C" void kernel_launch(void* const* d_in, const int* in_sizes, int n_in,
                              void* d_out, int out_size)
{
    const int*   gt_labels      = (const int*)d_in[0];
    const float* gt_boxes       = (const float*)d_in[1];
    const float* anchors_cxcywh = (const float*)d_in[2];
    const float* anchors_xyxy   = (const float*)d_in[3];

    const int A = in_sizes[2] / 4;
    const int B = in_sizes[0] / NGT;

    const int chunks = (A + ANCHORS_PER_BLOCK - 1) / ANCHORS_PER_BLOCK;

    init_kernel<<<(B * NGT + 255) / 256, 256>>>(B * NGT);
    iou_kernel<<<dim3(chunks, B), TPB>>>(gt_boxes, anchors_xyxy, A);
    override_kernel<<<B, 128>>>(A);
    encode_kernel<<<dim3((A + 255) / 256, B), 256>>>(gt_labels, gt_boxes,
                                                     anchors_cxcywh,
                                                     (float*)d_out, A, B);
}